// round 10
// baseline (speedup 1.0000x reference)
#include <cuda_runtime.h>
#include <cuda_bf16.h>

// out[n, j] = x[n, j] + (1/512) * sum_{k=512..1023} x[n, k]
// x: [131072, 1024] f32, out: [131072, 512] f32
//
// Best-profiled structure (R1): one 128-thread block per row.
//   - both float4 loads front-batched (MLP_p1=2)
//   - __ldcg loads: bypass L1 (zero-reuse streaming data; L1 fill is pure
//     overhead), cache in L2 only. Final unprobed cache-policy cell.
//   - warp shfl reduce -> 4 smem partials -> one __syncthreads -> add, store.
// Kernel operates at the HBM read/write-turnaround ceiling (~88% of spec);
// traffic (768 MiB) is irreducible.

static constexpr int ROW_IN  = 1024;
static constexpr int ROW_OUT = 512;
static constexpr int THREADS = 128;

__global__ __launch_bounds__(THREADS)
void projection_kernel(const float* __restrict__ x,
                       float* __restrict__ out)
{
    int tid  = threadIdx.x;
    int lane = tid & 31;
    int warp = tid >> 5;

    const float4* xrow = reinterpret_cast<const float4*>(x + (size_t)blockIdx.x * ROW_IN);
    float4*       orow = reinterpret_cast<float4*>(out + (size_t)blockIdx.x * ROW_OUT);

    // front-batch both loads, L1-bypass (L2-only) policy
    float4 t = __ldcg(&xrow[128 + tid]);   // tail, feeds reduction
    float4 h = __ldcg(&xrow[tid]);         // head, held for the add

    float s = (t.x + t.y) + (t.z + t.w);

    #pragma unroll
    for (int off = 16; off > 0; off >>= 1)
        s += __shfl_xor_sync(0xFFFFFFFFu, s, off);

    __shared__ float partial[4];
    if (lane == 0) partial[warp] = s;
    __syncthreads();

    float total = (partial[0] + partial[1]) + (partial[2] + partial[3]);
    float mean = total * (1.0f / 512.0f);

    h.x += mean; h.y += mean; h.z += mean; h.w += mean;

    orow[tid] = h;
}

extern "C" void kernel_launch(void* const* d_in, const int* in_sizes, int n_in,
                              void* d_out, int out_size)
{
    const float* x = (const float*)d_in[0];
    float* out = (float*)d_out;

    int n_rows = in_sizes[0] / ROW_IN;   // 131072

    projection_kernel<<<n_rows, THREADS>>>(x, out);
}

// round 11
// speedup vs baseline: 1.0120x; 1.0120x over previous
#include <cuda_runtime.h>
#include <cuda_bf16.h>

// out[n, j] = x[n, j] + (1/512) * sum_{k=512..1023} x[n, k]
// x: [131072, 1024] f32, out: [131072, 512] f32
//
// Final configuration: combines the two independently-best axes measured
// over 10 rounds:
//   - SHAPE: 256-thread block = 2 independent rows x 128 threads, one
//     __syncthreads (best wall time: 65536 blocks halve launch/wave
//     overhead vs 1 row/block)
//   - CACHE: __ldcg loads — L1 bypass, L2-only (best profiled DRAM%:
//     zero-reuse streaming data makes L1 fill pure overhead); plain store.
// MLP_p1=2 per thread (below cross-CTA L1tex contention knee).
// Kernel sits at the HBM read/write-turnaround ceiling (~88% of 8TB/s);
// traffic (768 MiB) is irreducible — every byte touched exactly once.

static constexpr int ROW_IN  = 1024;
static constexpr int ROW_OUT = 512;
static constexpr int THREADS = 256;   // 2 rows x 128 threads

__global__ __launch_bounds__(THREADS)
void projection_kernel(const float* __restrict__ x,
                       float* __restrict__ out)
{
    int sub  = threadIdx.x >> 7;           // row group 0/1
    int tid  = threadIdx.x & 127;          // 0..127 within group
    int lane = threadIdx.x & 31;
    int warp = (threadIdx.x >> 5) & 3;     // warp within group

    size_t row = (size_t)blockIdx.x * 2 + sub;

    const float4* xrow = reinterpret_cast<const float4*>(x + row * ROW_IN);
    float4*       orow = reinterpret_cast<float4*>(out + row * ROW_OUT);

    // front-batch both loads, L1-bypass (L2-only) policy
    float4 t = __ldcg(&xrow[128 + tid]);   // tail, feeds reduction
    float4 h = __ldcg(&xrow[tid]);         // head, held for the add

    float s = (t.x + t.y) + (t.z + t.w);

    #pragma unroll
    for (int off = 16; off > 0; off >>= 1)
        s += __shfl_xor_sync(0xFFFFFFFFu, s, off);

    __shared__ float partial[2][4];
    if (lane == 0) partial[sub][warp] = s;
    __syncthreads();

    float total = (partial[sub][0] + partial[sub][1])
                + (partial[sub][2] + partial[sub][3]);
    float mean = total * (1.0f / 512.0f);

    h.x += mean; h.y += mean; h.z += mean; h.w += mean;

    orow[tid] = h;
}

extern "C" void kernel_launch(void* const* d_in, const int* in_sizes, int n_in,
                              void* d_out, int out_size)
{
    const float* x = (const float*)d_in[0];
    float* out = (float*)d_out;

    int n_rows = in_sizes[0] / ROW_IN;   // 131072, even
    int blocks = n_rows / 2;             // 65536

    projection_kernel<<<blocks, THREADS>>>(x, out);
}